// round 2
// baseline (speedup 1.0000x reference)
#include <cuda_runtime.h>

// CapsNet dynamic routing, fully fused.
// Key identity: logits b_t = u * (v_1 + ... + v_{t-1})  (elementwise, v broadcast
// over IC), so u (189 MB) is never materialized. Each pass recomputes
// u[b,i,o,d] = sum_k W[i,o,d,k] * x[b,i,k] with W held in registers.

namespace {
constexpr int B_  = 256;
constexpr int IC_ = 1152;
constexpr int ID_ = 8;
constexpr int OC_ = 10;
constexpr int OD_ = 16;
constexpr int SOD = B_ * OD_ * OC_;   // 40960 floats per s / V buffer

constexpr int IBLK = 16;              // i's per CTA (one per lane of a 16-group)
constexpr int BCH  = 64;              // batches per CTA
constexpr int NIB  = IC_ / IBLK;      // 72
constexpr int NBCH = B_ / BCH;        // 4
}

// Scratch (allocation-free: __device__ globals)
__device__ float g_s[3][SOD];    // s for iterations 1..3, layout [b][d][o]
__device__ float g_Vsum[SOD];    // running sum of v, layout [b][d][o]
__device__ float g_Vs[SOD];      // Vsum * log2(e)  (pre-scaled for ex2)

__device__ __forceinline__ float fast_ex2(float x) {
    float y; asm("ex2.approx.ftz.f32 %0, %1;" : "=f"(y) : "f"(x)); return y;
}
__device__ __forceinline__ float fast_rcp(float x) {
    float y; asm("rcp.approx.ftz.f32 %0, %1;" : "=f"(y) : "f"(x)); return y;
}
__device__ __forceinline__ float fast_rsqrt(float x) {
    float y; asm("rsqrt.approx.ftz.f32 %0, %1;" : "=f"(y) : "f"(x)); return y;
}

__global__ void zero_kernel() {
    int idx = blockIdx.x * 256 + threadIdx.x;
    if (idx < SOD) {
        g_s[0][idx] = 0.f;
        g_s[1][idx] = 0.f;
        g_s[2][idx] = 0.f;
        g_Vsum[idx] = 0.f;
    }
}

// One routing pass: s[b,d,o] = sum_i c[b,i,o,d] * u[b,i,o,d]
// FIRST: c = 1/OC (softmax of zero logits). Otherwise c = softmax_o(u * Vsum).
template<bool FIRST>
__global__ __launch_bounds__(256, 1) void route_kernel(
    const float* __restrict__ x,   // [B, IC, ID]
    const float* __restrict__ W,   // [IC, OC, OD, ID]
    int which)                     // which g_s buffer to accumulate into
{
    float* __restrict__ s_out = g_s[which];

    const int t   = threadIdx.x;
    const int i_l = t & 15;        // lane within 16-group = i offset
    const int d   = t >> 4;        // 0..15
    const int i   = blockIdx.x * IBLK + i_l;
    const int b0  = blockIdx.y * BCH;

    // Pin this thread's W slice in registers: W[i, o, d, 0..7] for o=0..9.
    float Wr[OC_][ID_];
#pragma unroll
    for (int o = 0; o < OC_; o++) {
        const float4* wp = reinterpret_cast<const float4*>(
            W + (((size_t)i * OC_ + o) * OD_ + d) * ID_);
        float4 wa = wp[0], wb = wp[1];
        Wr[o][0] = wa.x; Wr[o][1] = wa.y; Wr[o][2] = wa.z; Wr[o][3] = wa.w;
        Wr[o][4] = wb.x; Wr[o][5] = wb.y; Wr[o][6] = wb.z; Wr[o][7] = wb.w;
    }

    for (int b = b0; b < b0 + BCH; b++) {
        const float4* xp = reinterpret_cast<const float4*>(
            x + ((size_t)b * IC_ + i) * ID_);
        float4 xa = xp[0], xb = xp[1];
        float xv[ID_] = {xa.x, xa.y, xa.z, xa.w, xb.x, xb.y, xb.z, xb.w};

        // u[o] = <W[i,o,d,:], x[b,i,:]>
        float u[OC_];
#pragma unroll
        for (int o = 0; o < OC_; o++) {
            float acc = Wr[o][0] * xv[0];
#pragma unroll
            for (int k = 1; k < ID_; k++) acc = fmaf(Wr[o][k], xv[k], acc);
            u[o] = acc;
        }

        float contrib[OC_];
        if (FIRST) {
#pragma unroll
            for (int o = 0; o < OC_; o++) contrib[o] = u[o];
        } else {
            // thread-local softmax over o against V (pre-scaled by log2e)
            const float* Vp = g_Vs + ((size_t)b * OD_ + d) * OC_;
            float e[OC_];
            float Z = 0.f;
#pragma unroll
            for (int o = 0; o < OC_; o++) {
                e[o] = fast_ex2(u[o] * Vp[o]);
                Z += e[o];
            }
            float r = fast_rcp(Z);
#pragma unroll
            for (int o = 0; o < OC_; o++) contrib[o] = u[o] * (e[o] * r);
        }

        // reduce over the 16 i-lanes (same d) via butterfly
#pragma unroll
        for (int o = 0; o < OC_; o++) {
#pragma unroll
            for (int off = 8; off > 0; off >>= 1)
                contrib[o] += __shfl_xor_sync(0xffffffffu, contrib[o], off);
        }

        if (i_l == 0) {
            float* sp = s_out + ((size_t)b * OD_ + d) * OC_;
#pragma unroll
            for (int o = 0; o < OC_; o++)
                atomicAdd(sp + o, FIRST ? contrib[o] * (1.0f / OC_) : contrib[o]);
        }
    }
}

// squash(s) per (b,o) over d; update Vsum / Vs, or write final output.
__global__ void squash_kernel(int which, float* __restrict__ out, int final_) {
    const float* __restrict__ s = g_s[which];
    int t  = blockIdx.x * 256 + threadIdx.x;   // SOD threads exactly
    int d  = t & 15;
    int bo = t >> 4;
    int o  = bo % OC_;
    int b  = bo / OC_;

    float sv = s[((size_t)b * OD_ + d) * OC_ + o];
    float l2 = sv * sv;
#pragma unroll
    for (int off = 8; off > 0; off >>= 1)
        l2 += __shfl_xor_sync(0xffffffffu, l2, off);

    // squash coef = ||s|| / (1 + ||s||^2)   (since s*l2/(1+l2)/sqrt(l2))
    float coef = l2 * fast_rsqrt(l2) * fast_rcp(1.f + l2);
    float v = sv * coef;

    if (final_) {
        out[((size_t)b * OC_ + o) * OD_ + d] = v;   // output [B, OC, OD]
    } else {
        int idx = ((size_t)b * OD_ + d) * OC_ + o;
        float nv = g_Vsum[idx] + v;
        g_Vsum[idx] = nv;
        g_Vs[idx] = nv * 1.4426950408889634f;       // * log2(e) for ex2
    }
}

extern "C" void kernel_launch(void* const* d_in, const int* in_sizes, int n_in,
                              void* d_out, int out_size) {
    const float* x = (const float*)d_in[0];   // [256,1152,8]
    const float* W = (const float*)d_in[1];   // [1152,10,16,8]
    float* out = (float*)d_out;               // [256,10,16]

    dim3 rg(NIB, NBCH);
    int sgrid = SOD / 256;                    // 160 blocks, exact

    zero_kernel<<<sgrid, 256>>>();

    route_kernel<true><<<rg, 256>>>(x, W, 0);
    squash_kernel<<<sgrid, 256>>>(0, out, 0);

    route_kernel<false><<<rg, 256>>>(x, W, 1);
    squash_kernel<<<sgrid, 256>>>(1, out, 0);

    route_kernel<false><<<rg, 256>>>(x, W, 2);
    squash_kernel<<<sgrid, 256>>>(2, out, 1);
}